// round 6
// baseline (speedup 1.0000x reference)
#include <cuda_runtime.h>
#include <math.h>

#define TSEQ 2048
#define CEMB 2048
#define BATCH 2
#define NHEAD 16
#define NGRP 4
#define HD 128
#define QKVN 3072          // (16 + 2*4) * 128
#define FFN 8192
#define MROWS 4096         // B*T
#define SCALE 0.08838834764831845f  // 1/sqrt(128)

// ---------------- scratch (device globals: allocation-free rule) -------------
__device__ float g_xn1[MROWS * CEMB];
__device__ float g_xn2[MROWS * CEMB];
__device__ float g_qkv[MROWS * QKVN];
__device__ float g_y  [MROWS * CEMB];
__device__ float g_act[(size_t)MROWS * FFN];
__device__ float g_scores[(size_t)BATCH * NHEAD * TSEQ * TSEQ];

// ---------------- fused double LayerNorm (shared mean/var) -------------------
__global__ void __launch_bounds__(256) ln_kernel(
    const float* __restrict__ x,
    const float* __restrict__ w1, const float* __restrict__ b1,
    const float* __restrict__ w2, const float* __restrict__ b2)
{
    int row = blockIdx.x, tid = threadIdx.x;
    const float4* xr = (const float4*)(x + (size_t)row * CEMB);
    float4 a = xr[tid], b = xr[tid + 256];

    float s = a.x + a.y + a.z + a.w + b.x + b.y + b.z + b.w;
    float q = a.x*a.x + a.y*a.y + a.z*a.z + a.w*a.w
            + b.x*b.x + b.y*b.y + b.z*b.z + b.w*b.w;
    #pragma unroll
    for (int o = 16; o; o >>= 1) {
        s += __shfl_xor_sync(0xffffffffu, s, o);
        q += __shfl_xor_sync(0xffffffffu, q, o);
    }
    __shared__ float rs[8], rq[8], s_mu, s_rstd;
    int wid = tid >> 5, lane = tid & 31;
    if (!lane) { rs[wid] = s; rq[wid] = q; }
    __syncthreads();
    if (tid == 0) {
        float S = 0.f, Q = 0.f;
        #pragma unroll
        for (int i = 0; i < 8; i++) { S += rs[i]; Q += rq[i]; }
        float mu  = S * (1.0f / CEMB);
        float var = Q * (1.0f / CEMB) - mu * mu;
        s_mu = mu;
        s_rstd = rsqrtf(var + 1e-5f);
    }
    __syncthreads();
    float mu = s_mu, r = s_rstd;

    const float4* W1 = (const float4*)w1; const float4* B1 = (const float4*)b1;
    const float4* W2 = (const float4*)w2; const float4* B2 = (const float4*)b2;
    float4* o1 = (float4*)(g_xn1 + (size_t)row * CEMB);
    float4* o2 = (float4*)(g_xn2 + (size_t)row * CEMB);

    float4 w1a = W1[tid], w1b = W1[tid+256], b1a = B1[tid], b1b = B1[tid+256];
    float4 w2a = W2[tid], w2b = W2[tid+256], b2a = B2[tid], b2b = B2[tid+256];

    float4 na, nb;
    na.x = (a.x-mu)*r; na.y = (a.y-mu)*r; na.z = (a.z-mu)*r; na.w = (a.w-mu)*r;
    nb.x = (b.x-mu)*r; nb.y = (b.y-mu)*r; nb.z = (b.z-mu)*r; nb.w = (b.w-mu)*r;

    float4 t;
    t.x = na.x*w1a.x+b1a.x; t.y = na.y*w1a.y+b1a.y; t.z = na.z*w1a.z+b1a.z; t.w = na.w*w1a.w+b1a.w;
    o1[tid] = t;
    t.x = nb.x*w1b.x+b1b.x; t.y = nb.y*w1b.y+b1b.y; t.z = nb.z*w1b.z+b1b.z; t.w = nb.w*w1b.w+b1b.w;
    o1[tid+256] = t;
    t.x = na.x*w2a.x+b2a.x; t.y = na.y*w2a.y+b2a.y; t.z = na.z*w2a.z+b2a.z; t.w = na.w*w2a.w+b2a.w;
    o2[tid] = t;
    t.x = nb.x*w2b.x+b2b.x; t.y = nb.y*w2b.y+b2b.y; t.z = nb.z*w2b.z+b2b.z; t.w = nb.w*w2b.w+b2b.w;
    o2[tid+256] = t;
}

// ---------------- RoPE (in-place on q heads + k groups, first 32 dims) -------
__global__ void __launch_bounds__(320) rope_kernel(
    const float* __restrict__ cosb, const float* __restrict__ sinb)
{
    int row = blockIdx.x;              // 0..4095  (b*T + t)
    int t   = row & (TSEQ - 1);
    int tid = threadIdx.x;
    int head = tid >> 4;               // 0..19 (16 q heads, 4 k groups)
    int i    = tid & 15;

    float* base;
    if (head < 16) {
        int g = head >> 2, slot = head & 3;
        base = g_qkv + (size_t)row * QKVN + g * 768 + slot * 128;
    } else {
        int g = head - 16;
        base = g_qkv + (size_t)row * QKVN + g * 768 + 512;
    }
    float c1 = cosb[t*32 + i],      s1 = sinb[t*32 + i];
    float c2 = cosb[t*32 + i + 16], s2 = sinb[t*32 + i + 16];
    float x1 = base[i], x2 = base[i + 16];
    base[i]      = x1 * c1 - x2 * s1;
    base[i + 16] = x2 * c2 + x1 * s2;
}

// ---------------- generic 128x128x16 SGEMM with epilogues --------------------
enum { EPI_NONE = 0, EPI_RESID = 1, EPI_GELU = 2, EPI_ADDOUT = 3 };

template<int EPI>
__global__ void __launch_bounds__(256, 2) sgemm_kernel(
    const float* __restrict__ A, int lda,
    const float* __restrict__ B, int ldb,
    float* __restrict__ C, int ldc,
    const float* __restrict__ bias,
    const float* __restrict__ resid,
    int K)
{
    __shared__ float As[16][132];   // k-major (transposed), padded
    __shared__ float Bs[16][128];

    const int tid = threadIdx.x;
    const int m0 = blockIdx.y * 128;
    const int n0 = blockIdx.x * 128;
    const float* Ab = A + (size_t)m0 * lda;
    const float* Bb = B + n0;

    const int ar0 = tid >> 2, akq = (tid & 3) * 4;
    const int ar1 = ar0 + 64;
    const int br0 = tid >> 5, bnq = (tid & 31) * 4;
    const int br1 = br0 + 8;

    const float* aP0 = Ab + (size_t)ar0 * lda + akq;
    const float* aP1 = Ab + (size_t)ar1 * lda + akq;
    const float* bP0 = Bb + (size_t)br0 * ldb + bnq;
    const float* bP1 = Bb + (size_t)br1 * ldb + bnq;

    const int tx = tid & 15, ty = tid >> 4;
    float acc[8][8];
    #pragma unroll
    for (int i = 0; i < 8; i++)
        #pragma unroll
        for (int j = 0; j < 8; j++) acc[i][j] = 0.f;

    for (int k0 = 0; k0 < K; k0 += 16) {
        float4 a0 = *(const float4*)(aP0 + k0);
        float4 a1 = *(const float4*)(aP1 + k0);
        float4 b0 = *(const float4*)(bP0 + (size_t)k0 * ldb);
        float4 b1 = *(const float4*)(bP1 + (size_t)k0 * ldb);
        As[akq+0][ar0] = a0.x; As[akq+1][ar0] = a0.y; As[akq+2][ar0] = a0.z; As[akq+3][ar0] = a0.w;
        As[akq+0][ar1] = a1.x; As[akq+1][ar1] = a1.y; As[akq+2][ar1] = a1.z; As[akq+3][ar1] = a1.w;
        *(float4*)&Bs[br0][bnq] = b0;
        *(float4*)&Bs[br1][bnq] = b1;
        __syncthreads();
        #pragma unroll
        for (int kk = 0; kk < 16; kk++) {
            float a[8], b[8];
            *(float4*)(a)     = *(const float4*)&As[kk][ty*8];
            *(float4*)(a + 4) = *(const float4*)&As[kk][ty*8 + 4];
            *(float4*)(b)     = *(const float4*)&Bs[kk][tx*8];
            *(float4*)(b + 4) = *(const float4*)&Bs[kk][tx*8 + 4];
            #pragma unroll
            for (int i = 0; i < 8; i++)
                #pragma unroll
                for (int j = 0; j < 8; j++)
                    acc[i][j] = fmaf(a[i], b[j], acc[i][j]);
        }
        __syncthreads();
    }

    #pragma unroll
    for (int i = 0; i < 8; i++) {
        int m = m0 + ty*8 + i;
        float* Crow = C + (size_t)m * ldc + n0 + tx*8;
        const float* Rrow = (EPI == EPI_RESID) ? (resid + (size_t)m * ldc + n0 + tx*8) : nullptr;
        #pragma unroll
        for (int j = 0; j < 8; j++) {
            float v = acc[i][j] + bias[n0 + tx*8 + j];
            if (EPI == EPI_RESID)  v += Rrow[j];
            if (EPI == EPI_GELU)   v = 0.5f * v * (1.0f + erff(v * 0.70710678118654752f));
            if (EPI == EPI_ADDOUT) v += Crow[j];
            Crow[j] = v;
        }
    }
}

// ---------------- attention: S = Q K^T (causal lower triangle only) ----------
__global__ void __launch_bounds__(256, 2) attn_scores_kernel()
{
    int si = blockIdx.x, ti = blockIdx.y;
    if (si > ti) return;
    int bh = blockIdx.z;
    int b = bh >> 4, h = bh & 15, g = h >> 2, sl = h & 3;

    const float* Q  = g_qkv + (size_t)b*TSEQ*QKVN + g*768 + sl*128 + (size_t)ti*128*QKVN;
    const float* Kp = g_qkv + (size_t)b*TSEQ*QKVN + g*768 + 512    + (size_t)si*128*QKVN;

    __shared__ float Qs[16][132], Ks[16][132];
    int tid = threadIdx.x;
    const int r0 = tid >> 2, kq = (tid & 3) * 4, r1 = r0 + 64;
    const float* q0 = Q  + (size_t)r0 * QKVN + kq;
    const float* q1 = Q  + (size_t)r1 * QKVN + kq;
    const float* k0 = Kp + (size_t)r0 * QKVN + kq;
    const float* k1 = Kp + (size_t)r1 * QKVN + kq;

    const int tx = tid & 15, ty = tid >> 4;
    float acc[8][8];
    #pragma unroll
    for (int i = 0; i < 8; i++)
        #pragma unroll
        for (int j = 0; j < 8; j++) acc[i][j] = 0.f;

    for (int kb = 0; kb < 128; kb += 16) {
        float4 a0 = *(const float4*)(q0 + kb);
        float4 a1 = *(const float4*)(q1 + kb);
        float4 c0 = *(const float4*)(k0 + kb);
        float4 c1 = *(const float4*)(k1 + kb);
        Qs[kq+0][r0]=a0.x; Qs[kq+1][r0]=a0.y; Qs[kq+2][r0]=a0.z; Qs[kq+3][r0]=a0.w;
        Qs[kq+0][r1]=a1.x; Qs[kq+1][r1]=a1.y; Qs[kq+2][r1]=a1.z; Qs[kq+3][r1]=a1.w;
        Ks[kq+0][r0]=c0.x; Ks[kq+1][r0]=c0.y; Ks[kq+2][r0]=c0.z; Ks[kq+3][r0]=c0.w;
        Ks[kq+0][r1]=c1.x; Ks[kq+1][r1]=c1.y; Ks[kq+2][r1]=c1.z; Ks[kq+3][r1]=c1.w;
        __syncthreads();
        #pragma unroll
        for (int kk = 0; kk < 16; kk++) {
            float a[8], bb[8];
            *(float4*)(a)      = *(const float4*)&Qs[kk][ty*8];
            *(float4*)(a + 4)  = *(const float4*)&Qs[kk][ty*8 + 4];
            *(float4*)(bb)     = *(const float4*)&Ks[kk][tx*8];
            *(float4*)(bb + 4) = *(const float4*)&Ks[kk][tx*8 + 4];
            #pragma unroll
            for (int i = 0; i < 8; i++)
                #pragma unroll
                for (int j = 0; j < 8; j++)
                    acc[i][j] = fmaf(a[i], bb[j], acc[i][j]);
        }
        __syncthreads();
    }

    float* S = g_scores + (size_t)bh * TSEQ * TSEQ;
    #pragma unroll
    for (int i = 0; i < 8; i++) {
        int t = ti*128 + ty*8 + i;
        #pragma unroll
        for (int j = 0; j < 8; j++) {
            int s = si*128 + tx*8 + j;
            float v = acc[i][j] * SCALE;
            S[(size_t)t * TSEQ + s] = (s <= t) ? v : -3.0e38f;
        }
    }
}

// ---------------- row softmax (causal length, register-resident) -------------
__global__ void __launch_bounds__(128) softmax_kernel()
{
    int t = blockIdx.x, bh = blockIdx.y;
    float* row = g_scores + ((size_t)bh * TSEQ + t) * TSEQ;
    int cnt = (t >> 7) + 1;            // number of 128-wide chunks written
    int tid = threadIdx.x;

    float v[16];
    float mx = -3.4e38f;
    #pragma unroll
    for (int c = 0; c < 16; c++)
        if (c < cnt) { v[c] = row[c*128 + tid]; mx = fmaxf(mx, v[c]); }
    #pragma unroll
    for (int o = 16; o; o >>= 1) mx = fmaxf(mx, __shfl_xor_sync(0xffffffffu, mx, o));

    __shared__ float sm1[4], sm2[4];
    int wid = tid >> 5, lane = tid & 31;
    if (!lane) sm1[wid] = mx;
    __syncthreads();
    mx = fmaxf(fmaxf(sm1[0], sm1[1]), fmaxf(sm1[2], sm1[3]));

    float s = 0.f;
    #pragma unroll
    for (int c = 0; c < 16; c++)
        if (c < cnt) { v[c] = __expf(v[c] - mx); s += v[c]; }
    #pragma unroll
    for (int o = 16; o; o >>= 1) s += __shfl_xor_sync(0xffffffffu, s, o);
    if (!lane) sm2[wid] = s;
    __syncthreads();
    s = sm2[0] + sm2[1] + sm2[2] + sm2[3];

    float inv = 1.0f / s;
    #pragma unroll
    for (int c = 0; c < 16; c++)
        if (c < cnt) row[c*128 + tid] = v[c] * inv;
}

// ---------------- attention: Y = P V (triangular K loop) ---------------------
__global__ void __launch_bounds__(256, 2) attn_av_kernel()
{
    int ti = blockIdx.y, bh = blockIdx.z;
    int b = bh >> 4, h = bh & 15, g = h >> 2;

    const float* P = g_scores + (size_t)bh * TSEQ * TSEQ + (size_t)ti*128 * TSEQ;
    const float* V = g_qkv + (size_t)b*TSEQ*QKVN + g*768 + 640;

    __shared__ float Ps[16][132], Vs[16][128];
    int tid = threadIdx.x;
    const int ar0 = tid >> 2, akq = (tid & 3) * 4, ar1 = ar0 + 64;
    const int br0 = tid >> 5, bnq = (tid & 31) * 4, br1 = br0 + 8;

    const float* p0 = P + (size_t)ar0 * TSEQ + akq;
    const float* p1 = P + (size_t)ar1 * TSEQ + akq;
    const float* v0 = V + (size_t)br0 * QKVN + bnq;
    const float* v1 = V + (size_t)br1 * QKVN + bnq;

    const int tx = tid & 15, ty = tid >> 4;
    float acc[8][8];
    #pragma unroll
    for (int i = 0; i < 8; i++)
        #pragma unroll
        for (int j = 0; j < 8; j++) acc[i][j] = 0.f;

    int Kend = (ti + 1) * 128;
    for (int k0 = 0; k0 < Kend; k0 += 16) {
        float4 a0 = *(const float4*)(p0 + k0);
        float4 a1 = *(const float4*)(p1 + k0);
        float4 b0 = *(const float4*)(v0 + (size_t)k0 * QKVN);
        float4 b1 = *(const float4*)(v1 + (size_t)k0 * QKVN);
        Ps[akq+0][ar0]=a0.x; Ps[akq+1][ar0]=a0.y; Ps[akq+2][ar0]=a0.z; Ps[akq+3][ar0]=a0.w;
        Ps[akq+0][ar1]=a1.x; Ps[akq+1][ar1]=a1.y; Ps[akq+2][ar1]=a1.z; Ps[akq+3][ar1]=a1.w;
        *(float4*)&Vs[br0][bnq] = b0;
        *(float4*)&Vs[br1][bnq] = b1;
        __syncthreads();
        #pragma unroll
        for (int kk = 0; kk < 16; kk++) {
            float a[8], bb[8];
            *(float4*)(a)      = *(const float4*)&Ps[kk][ty*8];
            *(float4*)(a + 4)  = *(const float4*)&Ps[kk][ty*8 + 4];
            *(float4*)(bb)     = *(const float4*)&Vs[kk][tx*8];
            *(float4*)(bb + 4) = *(const float4*)&Vs[kk][tx*8 + 4];
            #pragma unroll
            for (int i = 0; i < 8; i++)
                #pragma unroll
                for (int j = 0; j < 8; j++)
                    acc[i][j] = fmaf(a[i], bb[j], acc[i][j]);
        }
        __syncthreads();
    }

    // y layout: [b*T + t, h*128 + d]  == [B,T,H,D] flattened to [B,T,C]
    float* Y = g_y + ((size_t)(b*TSEQ + ti*128)) * CEMB + h*128;
    #pragma unroll
    for (int i = 0; i < 8; i++)
        #pragma unroll
        for (int j = 0; j < 8; j++)
            Y[(size_t)(ty*8 + i) * CEMB + tx*8 + j] = acc[i][j];
}

// ---------------- launch ----------------------------------------------------
extern "C" void kernel_launch(void* const* d_in, const int* in_sizes, int n_in,
                              void* d_out, int out_size)
{
    (void)in_sizes; (void)n_in; (void)out_size;
    const float* x     = (const float*)d_in[0];
    const float* cosb  = (const float*)d_in[1];
    const float* sinb  = (const float*)d_in[2];
    const float* ln1w  = (const float*)d_in[3];
    const float* ln1b  = (const float*)d_in[4];
    const float* wqkv  = (const float*)d_in[5];
    const float* bqkv  = (const float*)d_in[6];
    const float* wproj = (const float*)d_in[7];
    const float* bproj = (const float*)d_in[8];
    const float* ln2w  = (const float*)d_in[9];
    const float* ln2b  = (const float*)d_in[10];
    const float* wfc1  = (const float*)d_in[11];
    const float* bfc1  = (const float*)d_in[12];
    const float* wfc2  = (const float*)d_in[13];
    const float* bfc2  = (const float*)d_in[14];
    float* out = (float*)d_out;

    float *xn1, *xn2, *qkv, *yv, *act;
    cudaGetSymbolAddress((void**)&xn1, g_xn1);
    cudaGetSymbolAddress((void**)&xn2, g_xn2);
    cudaGetSymbolAddress((void**)&qkv, g_qkv);
    cudaGetSymbolAddress((void**)&yv,  g_y);
    cudaGetSymbolAddress((void**)&act, g_act);

    // 1. LN1 + LN2 (shared statistics)
    ln_kernel<<<MROWS, 256>>>(x, ln1w, ln1b, ln2w, ln2b);

    // 2. QKV GEMM: [4096,2048] @ [2048,3072]
    sgemm_kernel<EPI_NONE><<<dim3(QKVN/128, MROWS/128), 256>>>(
        xn1, CEMB, wqkv, QKVN, qkv, QKVN, bqkv, nullptr, CEMB);

    // 3. RoPE in-place on q heads + k groups
    rope_kernel<<<MROWS, 320>>>(cosb, sinb);

    // 4. causal scores (lower-triangle tiles only), 5. softmax, 6. P·V
    attn_scores_kernel<<<dim3(16, 16, BATCH*NHEAD), 256>>>();
    softmax_kernel<<<dim3(TSEQ, BATCH*NHEAD), 128>>>();
    attn_av_kernel<<<dim3(1, 16, BATCH*NHEAD), 256>>>();

    // 7. proj GEMM, epilogue adds b_proj + x residual, writes d_out
    sgemm_kernel<EPI_RESID><<<dim3(CEMB/128, MROWS/128), 256>>>(
        yv, CEMB, wproj, CEMB, out, CEMB, bproj, x, CEMB);

    // 8. fc1 GEMM + exact GELU
    sgemm_kernel<EPI_GELU><<<dim3(FFN/128, MROWS/128), 256>>>(
        xn2, CEMB, wfc1, FFN, act, FFN, bfc1, nullptr, CEMB);

    // 9. fc2 GEMM, epilogue adds into d_out (mlp + (h + x))
    sgemm_kernel<EPI_ADDOUT><<<dim3(CEMB/128, MROWS/128), 256>>>(
        act, FFN, wfc2, CEMB, out, CEMB, bfc2, nullptr, FFN);
}